// round 10
// baseline (speedup 1.0000x reference)
#include <cuda_runtime.h>
#include <cuda_fp16.h>
#include <math.h>
#include <stdint.h>

#define MAXN 100000
#define MAXE 1600000
#define HDIM 128
#define CDIM 40
#define NBLK ((MAXN + 255) / 256)
#define PAD 136  // halves per smem row (128 + 8 pad -> conflict-free ldmatrix)

// ---------------- device scratch ----------------
__device__ __half g_linh[MAXN * HDIM];        // norm[row]*(h@W) fp16 (gather payload)
__device__ float  g_norm[MAXN];
__device__ int    g_deg[MAXN];
__device__ int    g_rowstart[MAXN + 1];
__device__ int    g_cursor[MAXN];
__device__ int    g_bsum[NBLK + 1];
__device__ int    g_csrS[MAXE];               // src index per edge, grouped by dst
__device__ float  g_bf[CDIM];
__device__ int    g_any;
__device__ __half g_Wh[4 * HDIM * HDIM];      // W^T fp16 hi images (3 layers + head)
__device__ __half g_Wl[4 * HDIM * HDIM];      // fp16( 2048*(W - hi) )

// ---------------- PTX helpers ----------------
__device__ __forceinline__ uint32_t smem_u32(const void* p) {
    uint32_t a;
    asm("{ .reg .u64 t; cvta.to.shared.u64 t, %1; cvt.u32.u64 %0, t; }" : "=r"(a) : "l"(p));
    return a;
}
__device__ __forceinline__ void ldx4(uint32_t* r, uint32_t addr) {
    asm volatile("ldmatrix.sync.aligned.m8n8.x4.shared.b16 {%0,%1,%2,%3}, [%4];"
                 : "=r"(r[0]), "=r"(r[1]), "=r"(r[2]), "=r"(r[3]) : "r"(addr));
}
__device__ __forceinline__ void mma_f16(float* d, const uint32_t* a, const uint32_t* b) {
    asm volatile("mma.sync.aligned.m16n8k16.row.col.f32.f16.f16.f32 "
                 "{%0,%1,%2,%3}, {%4,%5,%6,%7}, {%8,%9}, {%0,%1,%2,%3};"
                 : "+f"(d[0]), "+f"(d[1]), "+f"(d[2]), "+f"(d[3])
                 : "r"(a[0]), "r"(a[1]), "r"(a[2]), "r"(a[3]), "r"(b[0]), "r"(b[1]));
}
__device__ __forceinline__ int load_node(const void* ei, long long i, int is64) {
    if (is64) return (int)((const long long*)ei)[i];
    return ((const int*)ei)[i];
}

// ---------------- init + dtype detect (merged) ----------------
__global__ void init_detect_kernel(const int* __restrict__ ei32, int M, int nHalf) {
    int i = blockIdx.x * blockDim.x + threadIdx.x;
    if (i < M) g_deg[i] = 0;
    if (i == 0) g_any = 0;
    int found = 0;
    for (int j = i; j < nHalf; j += gridDim.x * blockDim.x)
        if (ei32[2 * j + 1] != 0) found = 1;
    if (found) atomicOr(&g_any, 1);
}
__global__ void count_deg_kernel(const void* __restrict__ ei, int E) {
    int is64 = (g_any == 0);
    int e = blockIdx.x * blockDim.x + threadIdx.x;
    if (e >= E) return;
    atomicAdd(&g_deg[load_node(ei, (long long)E + e, is64)], 1);
}
__global__ void norm_bsum_kernel(int M) {
    __shared__ int sd[256];
    int i = blockIdx.x * 256 + threadIdx.x;
    int d = (i < M) ? g_deg[i] : 0;
    if (i < M) g_norm[i] = rsqrtf((float)d + 1.0f);
    sd[threadIdx.x] = d;
    __syncthreads();
    for (int o = 128; o > 0; o >>= 1) {
        if (threadIdx.x < o) sd[threadIdx.x] += sd[threadIdx.x + o];
        __syncthreads();
    }
    if (threadIdx.x == 0) g_bsum[blockIdx.x] = sd[0];
}
// rowstart with in-kernel scan of block sums (each block re-sums prefix; L2-hot)
__global__ void rowstart_kernel(int M, int E, int nb) {
    __shared__ int sd[256];
    __shared__ int spre[256];
    int t = threadIdx.x;
    int pre = 0;
    for (int j = t; j < blockIdx.x; j += 256) pre += g_bsum[j];
    spre[t] = pre;
    __syncthreads();
    for (int o = 128; o > 0; o >>= 1) {
        if (t < o) spre[t] += spre[t + o];
        __syncthreads();
    }
    int blockBase = spre[0];

    int i = blockIdx.x * 256 + t;
    int v = (i < M) ? g_deg[i] : 0;
    sd[t] = v;
    __syncthreads();
    for (int o = 1; o < 256; o <<= 1) {
        int x = (t >= o) ? sd[t - o] : 0;
        __syncthreads();
        sd[t] += x;
        __syncthreads();
    }
    if (i < M) {
        g_rowstart[i] = blockBase + sd[t] - v;
        g_cursor[i] = 0;
    }
    if (i == 0) g_rowstart[M] = E;
}
__global__ void csr_fill_kernel(const void* __restrict__ ei, int E) {
    int is64 = (g_any == 0);
    int e = blockIdx.x * blockDim.x + threadIdx.x;
    if (e >= E) return;
    int s = load_node(ei, e, is64);
    int d = load_node(ei, (long long)E + e, is64);
    int pos = g_rowstart[d] + atomicAdd(&g_cursor[d], 1);
    g_csrS[pos] = s;
}

// ---------------- W splits (layers 1-3) + head fold, one kernel ----------------
__global__ void w_prep_kernel(const float* __restrict__ W1, const float* __restrict__ W2,
                              const float* __restrict__ W3,
                              const float* __restrict__ Wp1, const float* __restrict__ bp1,
                              const float* __restrict__ Wp2, const float* __restrict__ bp2) {
    int idx = blockIdx.x * 256 + threadIdx.x;
    if (idx < 3 * HDIM * HDIM) {
        int l = idx / (HDIM * HDIM);
        int r = idx - l * HDIM * HDIM;
        int n = r >> 7, k = r & 127;
        const float* W = (l == 0) ? W1 : (l == 1) ? W2 : W3;
        float v = W[k * HDIM + n];
        __half h = __float2half_rn(v);
        g_Wh[idx] = h;
        g_Wl[idx] = __float2half_rn((v - __half2float(h)) * 2048.0f);
    } else if (idx < 4 * HDIM * HDIM) {
        int id = idx - 3 * HDIM * HDIM;
        int n = id >> 7, k = id & 127;
        float v = 0.f;
        if (n < CDIM) {
            for (int j = 0; j < HDIM; j++)
                v = fmaf(Wp1[k * HDIM + j], Wp2[j * CDIM + n], v);
        }
        __half h = __float2half_rn(v);
        g_Wh[3 * HDIM * HDIM + id] = h;
        g_Wl[3 * HDIM * HDIM + id] = __float2half_rn((v - __half2float(h)) * 2048.0f);
    } else if (idx < 4 * HDIM * HDIM + CDIM) {
        int c = idx - 4 * HDIM * HDIM;
        float s = bp2[c];
        for (int j = 0; j < HDIM; j++)
            s = fmaf(bp1[j], Wp2[j * CDIM + c], s);
        g_bf[c] = s;
    }
}

// ---------------- fused gather + mma GEMM ----------------
// A-source:
//   useGather=0: external fp32 x
//   useGather=1: A[row] = relu(norm[row]*(sum_{src in CSR[row]} linh[src] + linh[row]) + bias)
// mode 0: writes g_linh = norm[row]*(A@W) (fp16)
// mode 1: head — logits + log_softmax fused, writes `out`
#define GEMM_SMEM (3 * 128 * PAD * 2)

__global__ __launch_bounds__(256, 2) void mma_gemm_kernel(
    const float* __restrict__ A_ext, const float* __restrict__ bias,
    float* __restrict__ out, int M, int useGather, int bsel, int mode)
{
    extern __shared__ __half sm[];
    __half* sA  = sm;                 // [128][PAD] fp16
    __half* sBh = sm + 128 * PAD;
    __half* sBl = sm + 2 * 128 * PAD;
    const __half* Bh = g_Wh + bsel * HDIM * HDIM;
    const __half* Bl = g_Wl + bsel * HDIM * HDIM;

    int tid = threadIdx.x;
    int lane = tid & 31, wid = tid >> 5;
    int rowBase = blockIdx.x * 128;

    // copy W images (32KB each)
    {
        const uint4* bh = (const uint4*)Bh;
        const uint4* bl = (const uint4*)Bl;
        for (int i = tid; i < 128 * 16; i += 256) {
            int n = i >> 4, c = i & 15;
            *(uint4*)(sBh + n * PAD + c * 8) = bh[i];
            *(uint4*)(sBl + n * PAD + c * 8) = bl[i];
        }
    }
    // A fill
    if (useGather) {
        // warp-per-row gather: warp w handles rows rowBase + w*16 .. +15
        const uint2* lp = (const uint2*)g_linh;
        float4 b4 = ((const float4*)bias)[lane];
        int r0 = rowBase + wid * 16;
        for (int r = 0; r < 16; r++) {
            int row = r0 + r;
            __half* dst = sA + (wid * 16 + r) * PAD + lane * 4;
            if (row < M) {
                int start = g_rowstart[row];
                int end   = g_rowstart[row + 1];
                uint2 sv = __ldg(lp + (size_t)row * 32 + lane);
                float2 a01 = __half22float2(*(__half2*)&sv.x);
                float2 a23 = __half22float2(*(__half2*)&sv.y);
                float4 acc = make_float4(a01.x, a01.y, a23.x, a23.y);

                for (int bse = start; bse < end; bse += 32) {
                    int idx = bse + lane;
                    int sidx = (idx < end) ? g_csrS[idx] : 0;
                    int cnt = min(32, end - bse);
                    int j = 0;
                    for (; j + 3 < cnt; j += 4) {
                        uint2 v[4];
                        #pragma unroll
                        for (int u = 0; u < 4; u++) {
                            int s = __shfl_sync(0xffffffffu, sidx, j + u);
                            v[u] = __ldg(lp + (size_t)s * 32 + lane);
                        }
                        #pragma unroll
                        for (int u = 0; u < 4; u++) {
                            float2 p = __half22float2(*(__half2*)&v[u].x);
                            float2 q = __half22float2(*(__half2*)&v[u].y);
                            acc.x += p.x; acc.y += p.y; acc.z += q.x; acc.w += q.y;
                        }
                    }
                    for (; j < cnt; j++) {
                        int s = __shfl_sync(0xffffffffu, sidx, j);
                        uint2 v0 = __ldg(lp + (size_t)s * 32 + lane);
                        float2 p = __half22float2(*(__half2*)&v0.x);
                        float2 q = __half22float2(*(__half2*)&v0.y);
                        acc.x += p.x; acc.y += p.y; acc.z += q.x; acc.w += q.y;
                    }
                }

                float n = g_norm[row];
                float h0 = fmaxf(fmaf(n, acc.x, b4.x), 0.f);
                float h1 = fmaxf(fmaf(n, acc.y, b4.y), 0.f);
                float h2 = fmaxf(fmaf(n, acc.z, b4.z), 0.f);
                float h3 = fmaxf(fmaf(n, acc.w, b4.w), 0.f);
                uint2 hv;
                *(__half2*)&hv.x = __floats2half2_rn(h0, h1);
                *(__half2*)&hv.y = __floats2half2_rn(h2, h3);
                *(uint2*)dst = hv;
            } else {
                *(uint2*)dst = make_uint2(0u, 0u);
            }
        }
    } else {
        int row = tid >> 1;
        int colBase = (tid & 1) * 64;
        int grow = rowBase + row;
        __half* dst = sA + row * PAD + colBase;
        const float4* Ap = (const float4*)(A_ext + (size_t)grow * HDIM + colBase);
        #pragma unroll
        for (int j = 0; j < 16; j++) {
            float4 v = make_float4(0.f, 0.f, 0.f, 0.f);
            if (grow < M) v = Ap[j];
            __half2 h01 = __floats2half2_rn(v.x, v.y);
            __half2 h23 = __floats2half2_rn(v.z, v.w);
            *(__half2*)(dst + j * 4)     = h01;
            *(__half2*)(dst + j * 4 + 2) = h23;
        }
    }
    __syncthreads();

    int wm = (wid & 3) * 32;
    int wn = (wid >> 2) * 64;

    uint32_t sbase = smem_u32(sm);
    int a_r = lane & 15;
    int a_k = (lane >> 4) * 8;
    int b_n = ((lane >> 4) & 1) * 8 + (lane & 7);
    int b_k = ((lane >> 3) & 1) * 8;

    uint32_t aA  = sbase + ((wm + a_r) * PAD + a_k) * 2;
    uint32_t aBh = sbase + 128 * PAD * 2 + ((wn + b_n) * PAD + b_k) * 2;
    uint32_t aBl = aBh + 128 * PAD * 2;

    const __half2 SC = __float2half2_rn(4.8828125e-4f);  // 2^-11
    const uint32_t scu = *(const uint32_t*)&SC;

    float d[2][8][4];
    #pragma unroll
    for (int mt = 0; mt < 2; mt++)
        #pragma unroll
        for (int nt = 0; nt < 8; nt++)
            #pragma unroll
            for (int r = 0; r < 4; r++) d[mt][nt][r] = 0.f;

    #pragma unroll
    for (int ks = 0; ks < 8; ks++) {
        uint32_t a[2][4], as[2][4], b[4][4];
        uint32_t koff = (uint32_t)(ks * 16 * 2);
        #pragma unroll
        for (int mt = 0; mt < 2; mt++) {
            ldx4(a[mt], aA + (uint32_t)(mt * 16 * PAD * 2) + koff);
            #pragma unroll
            for (int r = 0; r < 4; r++) {
                __half2 av = *(__half2*)&a[mt][r];
                __half2 sv = __hmul2(av, *(const __half2*)&scu);
                as[mt][r] = *(uint32_t*)&sv;
            }
        }
        #pragma unroll
        for (int np = 0; np < 4; np++)
            ldx4(b[np], aBh + (uint32_t)(np * 16 * PAD * 2) + koff);
        #pragma unroll
        for (int mt = 0; mt < 2; mt++)
            #pragma unroll
            for (int nt = 0; nt < 8; nt++)
                mma_f16(d[mt][nt], a[mt], &b[nt >> 1][(nt & 1) * 2]);
        #pragma unroll
        for (int np = 0; np < 4; np++)
            ldx4(b[np], aBl + (uint32_t)(np * 16 * PAD * 2) + koff);
        #pragma unroll
        for (int mt = 0; mt < 2; mt++)
            #pragma unroll
            for (int nt = 0; nt < 8; nt++)
                mma_f16(d[mt][nt], as[mt], &b[nt >> 1][(nt & 1) * 2]);
    }

    int g = lane >> 2, t2 = (lane & 3) * 2;
    if (mode == 0) {
        #pragma unroll
        for (int mt = 0; mt < 2; mt++) {
            int r0 = rowBase + wm + mt * 16 + g;
            int r1 = r0 + 8;
            float n0 = (r0 < M) ? g_norm[r0] : 0.f;
            float n1 = (r1 < M) ? g_norm[r1] : 0.f;
            #pragma unroll
            for (int nt = 0; nt < 8; nt++) {
                int col = wn + nt * 8 + t2;
                if (r0 < M) {
                    __half2 hv = __floats2half2_rn(d[mt][nt][0] * n0, d[mt][nt][1] * n0);
                    *(__half2*)&g_linh[(size_t)r0 * HDIM + col] = hv;
                }
                if (r1 < M) {
                    __half2 hv = __floats2half2_rn(d[mt][nt][2] * n1, d[mt][nt][3] * n1);
                    *(__half2*)&g_linh[(size_t)r1 * HDIM + col] = hv;
                }
            }
        }
    } else {
        if (wn == 0) {
            float bv[5][2];
            #pragma unroll
            for (int nt = 0; nt < 5; nt++) {
                int col = nt * 8 + t2;
                bv[nt][0] = __ldg(g_bf + col);
                bv[nt][1] = __ldg(g_bf + col + 1);
            }
            #pragma unroll
            for (int mt = 0; mt < 2; mt++) {
                #pragma unroll
                for (int half = 0; half < 2; half++) {
                    int row = rowBase + wm + mt * 16 + g + half * 8;
                    int ri = half * 2;
                    float l[5][2];
                    float m = -1e30f;
                    #pragma unroll
                    for (int nt = 0; nt < 5; nt++) {
                        l[nt][0] = d[mt][nt][ri] + bv[nt][0];
                        l[nt][1] = d[mt][nt][ri + 1] + bv[nt][1];
                        m = fmaxf(m, fmaxf(l[nt][0], l[nt][1]));
                    }
                    m = fmaxf(m, __shfl_xor_sync(0xffffffffu, m, 1));
                    m = fmaxf(m, __shfl_xor_sync(0xffffffffu, m, 2));
                    float e = 0.f;
                    #pragma unroll
                    for (int nt = 0; nt < 5; nt++)
                        e += expf(l[nt][0] - m) + expf(l[nt][1] - m);
                    e += __shfl_xor_sync(0xffffffffu, e, 1);
                    e += __shfl_xor_sync(0xffffffffu, e, 2);
                    float ls = m + logf(e);
                    if (row < M) {
                        #pragma unroll
                        for (int nt = 0; nt < 5; nt++) {
                            int col = nt * 8 + t2;
                            *(float2*)(out + (size_t)row * CDIM + col) =
                                make_float2(l[nt][0] - ls, l[nt][1] - ls);
                        }
                    }
                }
            }
        }
    }
}

// ---------------- launch ----------------
extern "C" void kernel_launch(void* const* d_in, const int* in_sizes, int n_in,
                              void* d_out, int out_size)
{
    const float* x   = (const float*)d_in[0];
    const void*  ei  = d_in[1];
    const float* W1  = (const float*)d_in[2];
    const float* b1  = (const float*)d_in[3];
    const float* W2  = (const float*)d_in[4];
    const float* b2  = (const float*)d_in[5];
    const float* W3  = (const float*)d_in[6];
    const float* b3  = (const float*)d_in[7];
    const float* Wp1 = (const float*)d_in[8];
    const float* bp1 = (const float*)d_in[9];
    const float* Wp2 = (const float*)d_in[10];
    const float* bp2 = (const float*)d_in[11];
    float* out = (float*)d_out;

    int M = in_sizes[0] / HDIM;
    int E = in_sizes[1] / 2;
    int nb = (M + 255) / 256;

    cudaFuncSetAttribute(mma_gemm_kernel,
                         cudaFuncAttributeMaxDynamicSharedMemorySize, GEMM_SMEM);

    init_detect_kernel<<<nb, 256>>>((const int*)ei, M, E);
    count_deg_kernel<<<(E + 255) / 256, 256>>>(ei, E);
    norm_bsum_kernel<<<nb, 256>>>(M);
    rowstart_kernel<<<nb, 256>>>(M, E, nb);
    csr_fill_kernel<<<(E + 255) / 256, 256>>>(ei, E);
    w_prep_kernel<<<(4 * HDIM * HDIM + CDIM + 255) / 256, 256>>>(W1, W2, W3, Wp1, bp1, Wp2, bp2);

    int gemmGrid = (M + 127) / 128;

    // layer 1: GEMM from x
    mma_gemm_kernel<<<gemmGrid, 256, GEMM_SMEM>>>(x, nullptr, out, M, 0, 0, 0);
    // layer 2: gather(linh1, b1) + GEMM
    mma_gemm_kernel<<<gemmGrid, 256, GEMM_SMEM>>>(nullptr, b1, out, M, 1, 1, 0);
    // layer 3: gather(linh2, b2) + GEMM
    mma_gemm_kernel<<<gemmGrid, 256, GEMM_SMEM>>>(nullptr, b2, out, M, 1, 2, 0);
    // head: gather(linh3, b3) + GEMM + log_softmax
    mma_gemm_kernel<<<gemmGrid, 256, GEMM_SMEM>>>(nullptr, b3, out, M, 1, 3, 1);
}

// round 11
// speedup vs baseline: 1.5239x; 1.5239x over previous
#include <cuda_runtime.h>
#include <cuda_fp16.h>
#include <math.h>
#include <stdint.h>

#define MAXN 100000
#define MAXE 1600000
#define HDIM 128
#define CDIM 40
#define NBLK ((MAXN + 255) / 256)
#define PAD 136  // halves per smem row (128 + 8 pad -> conflict-free ldmatrix)

// ---------------- device scratch ----------------
__device__ __half g_linh[MAXN * HDIM];        // norm[row]*(h@W) fp16 (gather payload)
__device__ __half g_hh[MAXN * HDIM];          // layer output (post-ReLU) fp16
__device__ float  g_norm[MAXN];
__device__ int    g_deg[MAXN];
__device__ int    g_rowstart[MAXN + 1];
__device__ int    g_cursor[MAXN];
__device__ int    g_bsum[NBLK + 1];
__device__ int    g_csrS[MAXE];               // src index per edge, grouped by dst
__device__ float  g_bf[CDIM];
__device__ int    g_any;                      // starts 0; reset at end of each run
__device__ __half g_Wh[4 * HDIM * HDIM];      // W^T fp16 hi images (3 layers + head)
__device__ __half g_Wl[4 * HDIM * HDIM];      // fp16( 2048*(W - hi) )

// ---------------- PTX helpers ----------------
__device__ __forceinline__ uint32_t smem_u32(const void* p) {
    uint32_t a;
    asm("{ .reg .u64 t; cvta.to.shared.u64 t, %1; cvt.u32.u64 %0, t; }" : "=r"(a) : "l"(p));
    return a;
}
__device__ __forceinline__ void ldx4(uint32_t* r, uint32_t addr) {
    asm volatile("ldmatrix.sync.aligned.m8n8.x4.shared.b16 {%0,%1,%2,%3}, [%4];"
                 : "=r"(r[0]), "=r"(r[1]), "=r"(r[2]), "=r"(r[3]) : "r"(addr));
}
__device__ __forceinline__ void mma_f16(float* d, const uint32_t* a, const uint32_t* b) {
    asm volatile("mma.sync.aligned.m16n8k16.row.col.f32.f16.f16.f32 "
                 "{%0,%1,%2,%3}, {%4,%5,%6,%7}, {%8,%9}, {%0,%1,%2,%3};"
                 : "+f"(d[0]), "+f"(d[1]), "+f"(d[2]), "+f"(d[3])
                 : "r"(a[0]), "r"(a[1]), "r"(a[2]), "r"(a[3]), "r"(b[0]), "r"(b[1]));
}
__device__ __forceinline__ int load_node(const void* ei, long long i, int is64) {
    if (is64) return (int)((const long long*)ei)[i];
    return ((const int*)ei)[i];
}

// ---------------- merged prep: deg zero + dtype detect + W splits + head fold ----------------
// g_any is NOT zeroed here (it is 0 at process start and reset by the head kernel
// at the end of every run) -> no init/OR race.
__global__ void prep_kernel(const int* __restrict__ ei32, int M, int nHalf,
                            const float* __restrict__ W1, const float* __restrict__ W2,
                            const float* __restrict__ W3,
                            const float* __restrict__ Wp1, const float* __restrict__ bp1,
                            const float* __restrict__ Wp2, const float* __restrict__ bp2)
{
    int i = blockIdx.x * blockDim.x + threadIdx.x;
    if (i < M) g_deg[i] = 0;

    // dtype detection: int64 little-endian ids < 2^31 => all odd 32-bit words zero
    int found = 0;
    for (int j = i; j < nHalf; j += gridDim.x * blockDim.x)
        if (ei32[2 * j + 1] != 0) found = 1;
    if (found) atomicOr(&g_any, 1);

    // W splits
    if (i < 3 * HDIM * HDIM) {
        int l = i / (HDIM * HDIM);
        int r = i - l * HDIM * HDIM;
        int n = r >> 7, k = r & 127;
        const float* W = (l == 0) ? W1 : (l == 1) ? W2 : W3;
        float v = W[k * HDIM + n];
        __half h = __float2half_rn(v);
        g_Wh[i] = h;
        g_Wl[i] = __float2half_rn((v - __half2float(h)) * 2048.0f);
    } else if (i < 4 * HDIM * HDIM) {
        int id = i - 3 * HDIM * HDIM;
        int n = id >> 7, k = id & 127;
        float v = 0.f;
        if (n < CDIM) {
            for (int j = 0; j < HDIM; j++)
                v = fmaf(Wp1[k * HDIM + j], Wp2[j * CDIM + n], v);
        }
        __half h = __float2half_rn(v);
        g_Wh[3 * HDIM * HDIM + id] = h;
        g_Wl[3 * HDIM * HDIM + id] = __float2half_rn((v - __half2float(h)) * 2048.0f);
    } else if (i < 4 * HDIM * HDIM + CDIM) {
        int c = i - 4 * HDIM * HDIM;
        float s = bp2[c];
        for (int j = 0; j < HDIM; j++)
            s = fmaf(bp1[j], Wp2[j * CDIM + c], s);
        g_bf[c] = s;
    }
}

__global__ void count_deg_kernel(const void* __restrict__ ei, int E) {
    int is64 = (g_any == 0);
    int e = blockIdx.x * blockDim.x + threadIdx.x;
    if (e >= E) return;
    atomicAdd(&g_deg[load_node(ei, (long long)E + e, is64)], 1);
}
__global__ void norm_bsum_kernel(int M) {
    __shared__ int sd[256];
    int i = blockIdx.x * 256 + threadIdx.x;
    int d = (i < M) ? g_deg[i] : 0;
    if (i < M) g_norm[i] = rsqrtf((float)d + 1.0f);
    sd[threadIdx.x] = d;
    __syncthreads();
    for (int o = 128; o > 0; o >>= 1) {
        if (threadIdx.x < o) sd[threadIdx.x] += sd[threadIdx.x + o];
        __syncthreads();
    }
    if (threadIdx.x == 0) g_bsum[blockIdx.x] = sd[0];
}
// rowstart with in-kernel scan of block sums (each block re-sums prefix; L2-hot)
__global__ void rowstart_kernel(int M, int E) {
    __shared__ int sd[256];
    __shared__ int spre[256];
    int t = threadIdx.x;
    int pre = 0;
    for (int j = t; j < blockIdx.x; j += 256) pre += g_bsum[j];
    spre[t] = pre;
    __syncthreads();
    for (int o = 128; o > 0; o >>= 1) {
        if (t < o) spre[t] += spre[t + o];
        __syncthreads();
    }
    int blockBase = spre[0];

    int i = blockIdx.x * 256 + t;
    int v = (i < M) ? g_deg[i] : 0;
    sd[t] = v;
    __syncthreads();
    for (int o = 1; o < 256; o <<= 1) {
        int x = (t >= o) ? sd[t - o] : 0;
        __syncthreads();
        sd[t] += x;
        __syncthreads();
    }
    if (i < M) {
        g_rowstart[i] = blockBase + sd[t] - v;
        g_cursor[i] = 0;
    }
    if (i == 0) g_rowstart[M] = E;
}
__global__ void csr_fill_kernel(const void* __restrict__ ei, int E) {
    int is64 = (g_any == 0);
    int e = blockIdx.x * blockDim.x + threadIdx.x;
    if (e >= E) return;
    int s = load_node(ei, e, is64);
    int d = load_node(ei, (long long)E + e, is64);
    int pos = g_rowstart[d] + atomicAdd(&g_cursor[d], 1);
    g_csrS[pos] = s;
}

// ---------------- mma.sync GEMM: 2-term fp16 (A·Wh + (A*2^-11)·(Wl*2^11)) ----------------
// mode 0: out = norm[row]*(A@W) -> g_linh (fp16)
// mode 1: head — logits + log_softmax fused, writes `out`; resets g_any at end
#define GEMM_SMEM (3 * 128 * PAD * 2)

__global__ __launch_bounds__(256, 2) void mma_gemm_kernel(
    const float* __restrict__ A_ext, float* __restrict__ out,
    int M, int useInternal, int bsel, int mode)
{
    extern __shared__ __half sm[];
    __half* sA  = sm;                 // [128][PAD] fp16
    __half* sBh = sm + 128 * PAD;
    __half* sBl = sm + 2 * 128 * PAD;
    const __half* Bh = g_Wh + bsel * HDIM * HDIM;
    const __half* Bl = g_Wl + bsel * HDIM * HDIM;

    int tid = threadIdx.x;
    int rowBase = blockIdx.x * 128;

    {
        const uint4* bh = (const uint4*)Bh;
        const uint4* bl = (const uint4*)Bl;
        for (int i = tid; i < 128 * 16; i += 256) {
            int n = i >> 4, c = i & 15;
            *(uint4*)(sBh + n * PAD + c * 8) = bh[i];
            *(uint4*)(sBl + n * PAD + c * 8) = bl[i];
        }
    }
    {
        int row = tid >> 1;
        int colBase = (tid & 1) * 64;
        int grow = rowBase + row;
        __half* dst = sA + row * PAD + colBase;
        if (useInternal) {
            const uint4* Ap = (const uint4*)(g_hh + (size_t)grow * HDIM + colBase);
            #pragma unroll
            for (int j = 0; j < 8; j++) {
                uint4 v = make_uint4(0u, 0u, 0u, 0u);
                if (grow < M) v = Ap[j];
                *(uint4*)(dst + j * 8) = v;
            }
        } else {
            const float4* Ap = (const float4*)(A_ext + (size_t)grow * HDIM + colBase);
            #pragma unroll
            for (int j = 0; j < 16; j++) {
                float4 v = make_float4(0.f, 0.f, 0.f, 0.f);
                if (grow < M) v = Ap[j];
                __half2 h01 = __floats2half2_rn(v.x, v.y);
                __half2 h23 = __floats2half2_rn(v.z, v.w);
                *(__half2*)(dst + j * 4)     = h01;
                *(__half2*)(dst + j * 4 + 2) = h23;
            }
        }
    }
    __syncthreads();

    int lane = tid & 31, wid = tid >> 5;
    int wm = (wid & 3) * 32;
    int wn = (wid >> 2) * 64;

    uint32_t sbase = smem_u32(sm);
    int a_r = lane & 15;
    int a_k = (lane >> 4) * 8;
    int b_n = ((lane >> 4) & 1) * 8 + (lane & 7);
    int b_k = ((lane >> 3) & 1) * 8;

    uint32_t aA  = sbase + ((wm + a_r) * PAD + a_k) * 2;
    uint32_t aBh = sbase + 128 * PAD * 2 + ((wn + b_n) * PAD + b_k) * 2;
    uint32_t aBl = aBh + 128 * PAD * 2;

    const __half2 SC = __float2half2_rn(4.8828125e-4f);  // 2^-11
    const uint32_t scu = *(const uint32_t*)&SC;

    float d[2][8][4];
    #pragma unroll
    for (int mt = 0; mt < 2; mt++)
        #pragma unroll
        for (int nt = 0; nt < 8; nt++)
            #pragma unroll
            for (int r = 0; r < 4; r++) d[mt][nt][r] = 0.f;

    // head (mode 1): only cols < 64 hold data; wn==64 warps skip MMA entirely
    if (mode == 0 || wn == 0) {
        #pragma unroll
        for (int ks = 0; ks < 8; ks++) {
            uint32_t a[2][4], as[2][4], b[4][4];
            uint32_t koff = (uint32_t)(ks * 16 * 2);
            #pragma unroll
            for (int mt = 0; mt < 2; mt++) {
                ldx4(a[mt], aA + (uint32_t)(mt * 16 * PAD * 2) + koff);
                #pragma unroll
                for (int r = 0; r < 4; r++) {
                    __half2 av = *(__half2*)&a[mt][r];
                    __half2 sv = __hmul2(av, *(const __half2*)&scu);
                    as[mt][r] = *(uint32_t*)&sv;
                }
            }
            #pragma unroll
            for (int np = 0; np < 4; np++)
                ldx4(b[np], aBh + (uint32_t)(np * 16 * PAD * 2) + koff);
            #pragma unroll
            for (int mt = 0; mt < 2; mt++)
                #pragma unroll
                for (int nt = 0; nt < 8; nt++)
                    mma_f16(d[mt][nt], a[mt], &b[nt >> 1][(nt & 1) * 2]);
            #pragma unroll
            for (int np = 0; np < 4; np++)
                ldx4(b[np], aBl + (uint32_t)(np * 16 * PAD * 2) + koff);
            #pragma unroll
            for (int mt = 0; mt < 2; mt++)
                #pragma unroll
                for (int nt = 0; nt < 8; nt++)
                    mma_f16(d[mt][nt], as[mt], &b[nt >> 1][(nt & 1) * 2]);
        }
    }

    int g = lane >> 2, t2 = (lane & 3) * 2;
    if (mode == 0) {
        #pragma unroll
        for (int mt = 0; mt < 2; mt++) {
            int r0 = rowBase + wm + mt * 16 + g;
            int r1 = r0 + 8;
            float n0 = (r0 < M) ? g_norm[r0] : 0.f;
            float n1 = (r1 < M) ? g_norm[r1] : 0.f;
            #pragma unroll
            for (int nt = 0; nt < 8; nt++) {
                int col = wn + nt * 8 + t2;
                if (r0 < M) {
                    __half2 hv = __floats2half2_rn(d[mt][nt][0] * n0, d[mt][nt][1] * n0);
                    *(__half2*)&g_linh[(size_t)r0 * HDIM + col] = hv;
                }
                if (r1 < M) {
                    __half2 hv = __floats2half2_rn(d[mt][nt][2] * n1, d[mt][nt][3] * n1);
                    *(__half2*)&g_linh[(size_t)r1 * HDIM + col] = hv;
                }
            }
        }
    } else {
        if (wn == 0) {
            float bv[5][2];
            #pragma unroll
            for (int nt = 0; nt < 5; nt++) {
                int col = nt * 8 + t2;
                bv[nt][0] = __ldg(g_bf + col);
                bv[nt][1] = __ldg(g_bf + col + 1);
            }
            #pragma unroll
            for (int mt = 0; mt < 2; mt++) {
                #pragma unroll
                for (int half = 0; half < 2; half++) {
                    int row = rowBase + wm + mt * 16 + g + half * 8;
                    int ri = half * 2;
                    float l[5][2];
                    float m = -1e30f;
                    #pragma unroll
                    for (int nt = 0; nt < 5; nt++) {
                        l[nt][0] = d[mt][nt][ri] + bv[nt][0];
                        l[nt][1] = d[mt][nt][ri + 1] + bv[nt][1];
                        m = fmaxf(m, fmaxf(l[nt][0], l[nt][1]));
                    }
                    m = fmaxf(m, __shfl_xor_sync(0xffffffffu, m, 1));
                    m = fmaxf(m, __shfl_xor_sync(0xffffffffu, m, 2));
                    float e = 0.f;
                    #pragma unroll
                    for (int nt = 0; nt < 5; nt++)
                        e += expf(l[nt][0] - m) + expf(l[nt][1] - m);
                    e += __shfl_xor_sync(0xffffffffu, e, 1);
                    e += __shfl_xor_sync(0xffffffffu, e, 2);
                    float ls = m + logf(e);
                    if (row < M) {
                        #pragma unroll
                        for (int nt = 0; nt < 5; nt++) {
                            int col = nt * 8 + t2;
                            *(float2*)(out + (size_t)row * CDIM + col) =
                                make_float2(l[nt][0] - ls, l[nt][1] - ls);
                        }
                    }
                }
            }
        }
        // reset dtype flag for the next replay (deterministic, race-free)
        if (blockIdx.x == 0 && tid == 0) g_any = 0;
    }
}

// ---------------- gather: h = relu(norm[dst]*(sum linh[src] + self) + bias), fp16 out ----------------
__global__ __launch_bounds__(256) void gather_kernel(const float* __restrict__ bias, int M)
{
    int warp = (blockIdx.x * 256 + threadIdx.x) >> 5;
    int lane = threadIdx.x & 31;
    if (warp >= M) return;
    int row = warp;

    int start = g_rowstart[row];
    int end   = g_rowstart[row + 1];

    const uint2* lp = (const uint2*)g_linh;

    uint2 sv = __ldg(lp + (size_t)row * 32 + lane);
    float2 a01 = __half22float2(*(__half2*)&sv.x);
    float2 a23 = __half22float2(*(__half2*)&sv.y);
    float4 acc = make_float4(a01.x, a01.y, a23.x, a23.y);

    for (int bse = start; bse < end; bse += 32) {
        int idx = bse + lane;
        int sidx = (idx < end) ? g_csrS[idx] : 0;
        int cnt = min(32, end - bse);
        int j = 0;
        for (; j + 3 < cnt; j += 4) {
            uint2 v[4];
            #pragma unroll
            for (int u = 0; u < 4; u++) {
                int s = __shfl_sync(0xffffffffu, sidx, j + u);
                v[u] = __ldg(lp + (size_t)s * 32 + lane);
            }
            #pragma unroll
            for (int u = 0; u < 4; u++) {
                float2 p = __half22float2(*(__half2*)&v[u].x);
                float2 q = __half22float2(*(__half2*)&v[u].y);
                acc.x += p.x; acc.y += p.y; acc.z += q.x; acc.w += q.y;
            }
        }
        for (; j < cnt; j++) {
            int s = __shfl_sync(0xffffffffu, sidx, j);
            uint2 v0 = __ldg(lp + (size_t)s * 32 + lane);
            float2 p = __half22float2(*(__half2*)&v0.x);
            float2 q = __half22float2(*(__half2*)&v0.y);
            acc.x += p.x; acc.y += p.y; acc.z += q.x; acc.w += q.y;
        }
    }

    float n = g_norm[row];
    float4 b4 = ((const float4*)bias)[lane];
    float h0 = fmaxf(fmaf(n, acc.x, b4.x), 0.f);
    float h1 = fmaxf(fmaf(n, acc.y, b4.y), 0.f);
    float h2 = fmaxf(fmaf(n, acc.z, b4.z), 0.f);
    float h3 = fmaxf(fmaf(n, acc.w, b4.w), 0.f);
    uint2 hv;
    *(__half2*)&hv.x = __floats2half2_rn(h0, h1);
    *(__half2*)&hv.y = __floats2half2_rn(h2, h3);
    ((uint2*)g_hh)[(size_t)row * 32 + lane] = hv;
}

// ---------------- launch ----------------
extern "C" void kernel_launch(void* const* d_in, const int* in_sizes, int n_in,
                              void* d_out, int out_size)
{
    const float* x   = (const float*)d_in[0];
    const void*  ei  = d_in[1];
    const float* W1  = (const float*)d_in[2];
    const float* b1  = (const float*)d_in[3];
    const float* W2  = (const float*)d_in[4];
    const float* b2  = (const float*)d_in[5];
    const float* W3  = (const float*)d_in[6];
    const float* b3  = (const float*)d_in[7];
    const float* Wp1 = (const float*)d_in[8];
    const float* bp1 = (const float*)d_in[9];
    const float* Wp2 = (const float*)d_in[10];
    const float* bp2 = (const float*)d_in[11];
    float* out = (float*)d_out;

    int M = in_sizes[0] / HDIM;
    int E = in_sizes[1] / 2;
    int nb = (M + 255) / 256;
    int prepBlocks = nb > 257 ? nb : 257;  // cover both M range and W-split range

    cudaFuncSetAttribute(mma_gemm_kernel,
                         cudaFuncAttributeMaxDynamicSharedMemorySize, GEMM_SMEM);

    prep_kernel<<<prepBlocks, 256>>>((const int*)ei, M, E, W1, W2, W3, Wp1, bp1, Wp2, bp2);
    count_deg_kernel<<<(E + 255) / 256, 256>>>(ei, E);
    norm_bsum_kernel<<<nb, 256>>>(M);
    rowstart_kernel<<<nb, 256>>>(M, E);
    csr_fill_kernel<<<(E + 255) / 256, 256>>>(ei, E);

    int gemmGrid   = (M + 127) / 128;
    int gatherGrid = (M + 7) / 8;

    mma_gemm_kernel<<<gemmGrid, 256, GEMM_SMEM>>>(x, out, M, 0, 0, 0);
    gather_kernel<<<gatherGrid, 256>>>(b1, M);
    mma_gemm_kernel<<<gemmGrid, 256, GEMM_SMEM>>>(nullptr, out, M, 1, 1, 0);
    gather_kernel<<<gatherGrid, 256>>>(b2, M);
    mma_gemm_kernel<<<gemmGrid, 256, GEMM_SMEM>>>(nullptr, out, M, 1, 2, 0);
    gather_kernel<<<gatherGrid, 256>>>(b3, M);

    mma_gemm_kernel<<<gemmGrid, 256, GEMM_SMEM>>>(nullptr, out, M, 1, 3, 1);
}

// round 12
// speedup vs baseline: 1.6047x; 1.0530x over previous
#include <cuda_runtime.h>
#include <cuda_fp16.h>
#include <math.h>
#include <stdint.h>

#define MAXN 100000
#define MAXE 1600000
#define HDIM 128
#define CDIM 40
#define NBLK ((MAXN + 255) / 256)
#define PAD 136  // halves per smem row (128 + 8 pad -> conflict-free ldmatrix)

// ---------------- device scratch ----------------
__device__ __half g_linh[MAXN * HDIM];        // norm[row]*(h@W) fp16 (gather payload)
__device__ __half g_hh[MAXN * HDIM];          // layer output (post-ReLU) fp16
__device__ float  g_norm[MAXN];
__device__ int    g_deg[MAXN];
__device__ int    g_rowstart[MAXN + 1];
__device__ int    g_cursor[MAXN];
__device__ int    g_bsum[NBLK + 1];
__device__ int    g_csrS[MAXE];               // src index per edge, grouped by dst
__device__ float  g_bf[CDIM];
__device__ int    g_any;                      // starts 0; reset at end of each run
__device__ __half g_Wh[4 * HDIM * HDIM];      // W^T fp16 hi images (3 layers + head)
__device__ __half g_Wl[4 * HDIM * HDIM];      // fp16( 2048*(W - hi) ) (head uses slot 3)

// ---------------- PTX helpers ----------------
__device__ __forceinline__ uint32_t smem_u32(const void* p) {
    uint32_t a;
    asm("{ .reg .u64 t; cvta.to.shared.u64 t, %1; cvt.u32.u64 %0, t; }" : "=r"(a) : "l"(p));
    return a;
}
__device__ __forceinline__ void ldx4(uint32_t* r, uint32_t addr) {
    asm volatile("ldmatrix.sync.aligned.m8n8.x4.shared.b16 {%0,%1,%2,%3}, [%4];"
                 : "=r"(r[0]), "=r"(r[1]), "=r"(r[2]), "=r"(r[3]) : "r"(addr));
}
__device__ __forceinline__ void mma_f16(float* d, const uint32_t* a, const uint32_t* b) {
    asm volatile("mma.sync.aligned.m16n8k16.row.col.f32.f16.f16.f32 "
                 "{%0,%1,%2,%3}, {%4,%5,%6,%7}, {%8,%9}, {%0,%1,%2,%3};"
                 : "+f"(d[0]), "+f"(d[1]), "+f"(d[2]), "+f"(d[3])
                 : "r"(a[0]), "r"(a[1]), "r"(a[2]), "r"(a[3]), "r"(b[0]), "r"(b[1]));
}
__device__ __forceinline__ int load_node(const void* ei, long long i, int is64) {
    if (is64) return (int)((const long long*)ei)[i];
    return ((const int*)ei)[i];
}

// ---------------- merged prep: deg zero + dtype detect + W splits + head fold ----------------
__global__ void prep_kernel(const int* __restrict__ ei32, int M, int nHalf,
                            const float* __restrict__ W1, const float* __restrict__ W2,
                            const float* __restrict__ W3,
                            const float* __restrict__ Wp1, const float* __restrict__ bp1,
                            const float* __restrict__ Wp2, const float* __restrict__ bp2)
{
    int i = blockIdx.x * blockDim.x + threadIdx.x;
    if (i < M) g_deg[i] = 0;

    int found = 0;
    for (int j = i; j < nHalf; j += gridDim.x * blockDim.x)
        if (ei32[2 * j + 1] != 0) found = 1;
    if (found) atomicOr(&g_any, 1);

    if (i < 3 * HDIM * HDIM) {
        int l = i / (HDIM * HDIM);
        int r = i - l * HDIM * HDIM;
        int n = r >> 7, k = r & 127;
        const float* W = (l == 0) ? W1 : (l == 1) ? W2 : W3;
        g_Wh[i] = __float2half_rn(W[k * HDIM + n]);   // layers: single-term fp16
    } else if (i < 4 * HDIM * HDIM) {
        int id = i - 3 * HDIM * HDIM;
        int n = id >> 7, k = id & 127;
        float v = 0.f;
        if (n < CDIM) {
            for (int j = 0; j < HDIM; j++)
                v = fmaf(Wp1[k * HDIM + j], Wp2[j * CDIM + n], v);
        }
        __half h = __float2half_rn(v);
        g_Wh[3 * HDIM * HDIM + id] = h;
        g_Wl[3 * HDIM * HDIM + id] = __float2half_rn((v - __half2float(h)) * 2048.0f);
    } else if (i < 4 * HDIM * HDIM + CDIM) {
        int c = i - 4 * HDIM * HDIM;
        float s = bp2[c];
        for (int j = 0; j < HDIM; j++)
            s = fmaf(bp1[j], Wp2[j * CDIM + c], s);
        g_bf[c] = s;
    }
}

__global__ void count_deg_kernel(const void* __restrict__ ei, int E) {
    int is64 = (g_any == 0);
    int e = blockIdx.x * blockDim.x + threadIdx.x;
    if (e >= E) return;
    atomicAdd(&g_deg[load_node(ei, (long long)E + e, is64)], 1);
}
__global__ void norm_bsum_kernel(int M) {
    __shared__ int sd[256];
    int i = blockIdx.x * 256 + threadIdx.x;
    int d = (i < M) ? g_deg[i] : 0;
    if (i < M) g_norm[i] = rsqrtf((float)d + 1.0f);
    sd[threadIdx.x] = d;
    __syncthreads();
    for (int o = 128; o > 0; o >>= 1) {
        if (threadIdx.x < o) sd[threadIdx.x] += sd[threadIdx.x + o];
        __syncthreads();
    }
    if (threadIdx.x == 0) g_bsum[blockIdx.x] = sd[0];
}
__global__ void rowstart_kernel(int M, int E) {
    __shared__ int sd[256];
    __shared__ int spre[256];
    int t = threadIdx.x;
    int pre = 0;
    for (int j = t; j < blockIdx.x; j += 256) pre += g_bsum[j];
    spre[t] = pre;
    __syncthreads();
    for (int o = 128; o > 0; o >>= 1) {
        if (t < o) spre[t] += spre[t + o];
        __syncthreads();
    }
    int blockBase = spre[0];

    int i = blockIdx.x * 256 + t;
    int v = (i < M) ? g_deg[i] : 0;
    sd[t] = v;
    __syncthreads();
    for (int o = 1; o < 256; o <<= 1) {
        int x = (t >= o) ? sd[t - o] : 0;
        __syncthreads();
        sd[t] += x;
        __syncthreads();
    }
    if (i < M) {
        g_rowstart[i] = blockBase + sd[t] - v;
        g_cursor[i] = 0;
    }
    if (i == 0) g_rowstart[M] = E;
}
__global__ void csr_fill_kernel(const void* __restrict__ ei, int E) {
    int is64 = (g_any == 0);
    int e = blockIdx.x * blockDim.x + threadIdx.x;
    if (e >= E) return;
    int s = load_node(ei, e, is64);
    int d = load_node(ei, (long long)E + e, is64);
    int pos = g_rowstart[d] + atomicAdd(&g_cursor[d], 1);
    g_csrS[pos] = s;
}

// ---------------- mma.sync GEMM ----------------
// terms=1: D = A·Wh (layers).  terms=2: D = A·Wh + (A*2^-11)·(Wl*2^11) (head).
// mode 0: writes g_linh = norm[row]*(A@W).  mode 1: head logits + log_softmax -> out.
#define GEMM_SMEM_L (2 * 128 * PAD * 2)   // sA + sBh
#define GEMM_SMEM_H (3 * 128 * PAD * 2)   // sA + sBh + sBl

__global__ __launch_bounds__(256, 2) void mma_gemm_kernel(
    const float* __restrict__ A_ext, float* __restrict__ out,
    int M, int useInternal, int bsel, int mode, int terms)
{
    extern __shared__ __half sm[];
    __half* sA  = sm;                 // [128][PAD] fp16
    __half* sBh = sm + 128 * PAD;
    __half* sBl = sm + 2 * 128 * PAD; // only when terms==2
    const __half* Bh = g_Wh + bsel * HDIM * HDIM;
    const __half* Bl = g_Wl + bsel * HDIM * HDIM;

    int tid = threadIdx.x;
    int rowBase = blockIdx.x * 128;

    {
        const uint4* bh = (const uint4*)Bh;
        for (int i = tid; i < 128 * 16; i += 256) {
            int n = i >> 4, c = i & 15;
            *(uint4*)(sBh + n * PAD + c * 8) = bh[i];
        }
        if (terms == 2) {
            const uint4* bl = (const uint4*)Bl;
            for (int i = tid; i < 128 * 16; i += 256) {
                int n = i >> 4, c = i & 15;
                *(uint4*)(sBl + n * PAD + c * 8) = bl[i];
            }
        }
    }
    {
        int row = tid >> 1;
        int colBase = (tid & 1) * 64;
        int grow = rowBase + row;
        __half* dst = sA + row * PAD + colBase;
        if (useInternal) {
            const uint4* Ap = (const uint4*)(g_hh + (size_t)grow * HDIM + colBase);
            #pragma unroll
            for (int j = 0; j < 8; j++) {
                uint4 v = make_uint4(0u, 0u, 0u, 0u);
                if (grow < M) v = Ap[j];
                *(uint4*)(dst + j * 8) = v;
            }
        } else {
            const float4* Ap = (const float4*)(A_ext + (size_t)grow * HDIM + colBase);
            #pragma unroll
            for (int j = 0; j < 16; j++) {
                float4 v = make_float4(0.f, 0.f, 0.f, 0.f);
                if (grow < M) v = Ap[j];
                __half2 h01 = __floats2half2_rn(v.x, v.y);
                __half2 h23 = __floats2half2_rn(v.z, v.w);
                *(__half2*)(dst + j * 4)     = h01;
                *(__half2*)(dst + j * 4 + 2) = h23;
            }
        }
    }
    __syncthreads();

    int lane = tid & 31, wid = tid >> 5;
    int wm = (wid & 3) * 32;
    int wn = (wid >> 2) * 64;

    uint32_t sbase = smem_u32(sm);
    int a_r = lane & 15;
    int a_k = (lane >> 4) * 8;
    int b_n = ((lane >> 4) & 1) * 8 + (lane & 7);
    int b_k = ((lane >> 3) & 1) * 8;

    uint32_t aA  = sbase + ((wm + a_r) * PAD + a_k) * 2;
    uint32_t aBh = sbase + 128 * PAD * 2 + ((wn + b_n) * PAD + b_k) * 2;
    uint32_t aBl = aBh + 128 * PAD * 2;

    const __half2 SC = __float2half2_rn(4.8828125e-4f);  // 2^-11
    const uint32_t scu = *(const uint32_t*)&SC;

    float d[2][8][4];
    #pragma unroll
    for (int mt = 0; mt < 2; mt++)
        #pragma unroll
        for (int nt = 0; nt < 8; nt++)
            #pragma unroll
            for (int r = 0; r < 4; r++) d[mt][nt][r] = 0.f;

    // head (mode 1): only cols < 64 hold data; wn==64 warps skip MMA entirely
    if (mode == 0 || wn == 0) {
        #pragma unroll
        for (int ks = 0; ks < 8; ks++) {
            uint32_t a[2][4], b[4][4];
            uint32_t koff = (uint32_t)(ks * 16 * 2);
            #pragma unroll
            for (int mt = 0; mt < 2; mt++)
                ldx4(a[mt], aA + (uint32_t)(mt * 16 * PAD * 2) + koff);
            #pragma unroll
            for (int np = 0; np < 4; np++)
                ldx4(b[np], aBh + (uint32_t)(np * 16 * PAD * 2) + koff);
            #pragma unroll
            for (int mt = 0; mt < 2; mt++)
                #pragma unroll
                for (int nt = 0; nt < 8; nt++)
                    mma_f16(d[mt][nt], a[mt], &b[nt >> 1][(nt & 1) * 2]);
            if (terms == 2) {
                uint32_t as[2][4];
                #pragma unroll
                for (int mt = 0; mt < 2; mt++)
                    #pragma unroll
                    for (int r = 0; r < 4; r++) {
                        __half2 av = *(__half2*)&a[mt][r];
                        __half2 sv = __hmul2(av, *(const __half2*)&scu);
                        as[mt][r] = *(uint32_t*)&sv;
                    }
                #pragma unroll
                for (int np = 0; np < 4; np++)
                    ldx4(b[np], aBl + (uint32_t)(np * 16 * PAD * 2) + koff);
                #pragma unroll
                for (int mt = 0; mt < 2; mt++)
                    #pragma unroll
                    for (int nt = 0; nt < 8; nt++)
                        mma_f16(d[mt][nt], as[mt], &b[nt >> 1][(nt & 1) * 2]);
            }
        }
    }

    int g = lane >> 2, t2 = (lane & 3) * 2;
    if (mode == 0) {
        #pragma unroll
        for (int mt = 0; mt < 2; mt++) {
            int r0 = rowBase + wm + mt * 16 + g;
            int r1 = r0 + 8;
            float n0 = (r0 < M) ? g_norm[r0] : 0.f;
            float n1 = (r1 < M) ? g_norm[r1] : 0.f;
            #pragma unroll
            for (int nt = 0; nt < 8; nt++) {
                int col = wn + nt * 8 + t2;
                if (r0 < M) {
                    __half2 hv = __floats2half2_rn(d[mt][nt][0] * n0, d[mt][nt][1] * n0);
                    *(__half2*)&g_linh[(size_t)r0 * HDIM + col] = hv;
                }
                if (r1 < M) {
                    __half2 hv = __floats2half2_rn(d[mt][nt][2] * n1, d[mt][nt][3] * n1);
                    *(__half2*)&g_linh[(size_t)r1 * HDIM + col] = hv;
                }
            }
        }
    } else {
        if (wn == 0) {
            float bv[5][2];
            #pragma unroll
            for (int nt = 0; nt < 5; nt++) {
                int col = nt * 8 + t2;
                bv[nt][0] = __ldg(g_bf + col);
                bv[nt][1] = __ldg(g_bf + col + 1);
            }
            #pragma unroll
            for (int mt = 0; mt < 2; mt++) {
                #pragma unroll
                for (int half = 0; half < 2; half++) {
                    int row = rowBase + wm + mt * 16 + g + half * 8;
                    int ri = half * 2;
                    float l[5][2];
                    float m = -1e30f;
                    #pragma unroll
                    for (int nt = 0; nt < 5; nt++) {
                        l[nt][0] = d[mt][nt][ri] + bv[nt][0];
                        l[nt][1] = d[mt][nt][ri + 1] + bv[nt][1];
                        m = fmaxf(m, fmaxf(l[nt][0], l[nt][1]));
                    }
                    m = fmaxf(m, __shfl_xor_sync(0xffffffffu, m, 1));
                    m = fmaxf(m, __shfl_xor_sync(0xffffffffu, m, 2));
                    float e = 0.f;
                    #pragma unroll
                    for (int nt = 0; nt < 5; nt++)
                        e += expf(l[nt][0] - m) + expf(l[nt][1] - m);
                    e += __shfl_xor_sync(0xffffffffu, e, 1);
                    e += __shfl_xor_sync(0xffffffffu, e, 2);
                    float ls = m + logf(e);
                    if (row < M) {
                        #pragma unroll
                        for (int nt = 0; nt < 5; nt++) {
                            int col = nt * 8 + t2;
                            *(float2*)(out + (size_t)row * CDIM + col) =
                                make_float2(l[nt][0] - ls, l[nt][1] - ls);
                        }
                    }
                }
            }
        }
        if (blockIdx.x == 0 && tid == 0) g_any = 0;
    }
}

// ---------------- gather: h = relu(norm[dst]*(sum linh[src] + self) + bias), fp16 out ----------------
__global__ __launch_bounds__(256) void gather_kernel(const float* __restrict__ bias, int M)
{
    int warp = (blockIdx.x * 256 + threadIdx.x) >> 5;
    int lane = threadIdx.x & 31;
    if (warp >= M) return;
    int row = warp;

    int start = g_rowstart[row];
    int end   = g_rowstart[row + 1];

    const uint2* lp = (const uint2*)g_linh;

    uint2 sv = __ldg(lp + (size_t)row * 32 + lane);
    float2 a01 = __half22float2(*(__half2*)&sv.x);
    float2 a23 = __half22float2(*(__half2*)&sv.y);
    float4 acc = make_float4(a01.x, a01.y, a23.x, a23.y);

    for (int bse = start; bse < end; bse += 32) {
        int idx = bse + lane;
        int sidx = (idx < end) ? g_csrS[idx] : 0;
        int cnt = min(32, end - bse);
        int j = 0;
        for (; j + 3 < cnt; j += 4) {
            uint2 v[4];
            #pragma unroll
            for (int u = 0; u < 4; u++) {
                int s = __shfl_sync(0xffffffffu, sidx, j + u);
                v[u] = __ldg(lp + (size_t)s * 32 + lane);
            }
            #pragma unroll
            for (int u = 0; u < 4; u++) {
                float2 p = __half22float2(*(__half2*)&v[u].x);
                float2 q = __half22float2(*(__half2*)&v[u].y);
                acc.x += p.x; acc.y += p.y; acc.z += q.x; acc.w += q.y;
            }
        }
        for (; j < cnt; j++) {
            int s = __shfl_sync(0xffffffffu, sidx, j);
            uint2 v0 = __ldg(lp + (size_t)s * 32 + lane);
            float2 p = __half22float2(*(__half2*)&v0.x);
            float2 q = __half22float2(*(__half2*)&v0.y);
            acc.x += p.x; acc.y += p.y; acc.z += q.x; acc.w += q.y;
        }
    }

    float n = g_norm[row];
    float4 b4 = ((const float4*)bias)[lane];
    float h0 = fmaxf(fmaf(n, acc.x, b4.x), 0.f);
    float h1 = fmaxf(fmaf(n, acc.y, b4.y), 0.f);
    float h2 = fmaxf(fmaf(n, acc.z, b4.z), 0.f);
    float h3 = fmaxf(fmaf(n, acc.w, b4.w), 0.f);
    uint2 hv;
    *(__half2*)&hv.x = __floats2half2_rn(h0, h1);
    *(__half2*)&hv.y = __floats2half2_rn(h2, h3);
    ((uint2*)g_hh)[(size_t)row * 32 + lane] = hv;
}

// ---------------- launch ----------------
extern "C" void kernel_launch(void* const* d_in, const int* in_sizes, int n_in,
                              void* d_out, int out_size)
{
    const float* x   = (const float*)d_in[0];
    const void*  ei  = d_in[1];
    const float* W1  = (const float*)d_in[2];
    const float* b1  = (const float*)d_in[3];
    const float* W2  = (const float*)d_in[4];
    const float* b2  = (const float*)d_in[5];
    const float* W3  = (const float*)d_in[6];
    const float* b3  = (const float*)d_in[7];
    const float* Wp1 = (const float*)d_in[8];
    const float* bp1 = (const float*)d_in[9];
    const float* Wp2 = (const float*)d_in[10];
    const float* bp2 = (const float*)d_in[11];
    float* out = (float*)d_out;

    int M = in_sizes[0] / HDIM;
    int E = in_sizes[1] / 2;
    int nb = (M + 255) / 256;
    int prepBlocks = nb > 257 ? nb : 257;

    cudaFuncSetAttribute(mma_gemm_kernel,
                         cudaFuncAttributeMaxDynamicSharedMemorySize, GEMM_SMEM_H);

    prep_kernel<<<prepBlocks, 256>>>((const int*)ei, M, E, W1, W2, W3, Wp1, bp1, Wp2, bp2);
    count_deg_kernel<<<(E + 255) / 256, 256>>>(ei, E);
    norm_bsum_kernel<<<nb, 256>>>(M);
    rowstart_kernel<<<nb, 256>>>(M, E);
    csr_fill_kernel<<<(E + 255) / 256, 256>>>(ei, E);

    int gemmGrid   = (M + 127) / 128;
    int gatherGrid = (M + 7) / 8;

    mma_gemm_kernel<<<gemmGrid, 256, GEMM_SMEM_L>>>(x, out, M, 0, 0, 0, 1);
    gather_kernel<<<gatherGrid, 256>>>(b1, M);
    mma_gemm_kernel<<<gemmGrid, 256, GEMM_SMEM_L>>>(nullptr, out, M, 1, 1, 0, 1);
    gather_kernel<<<gatherGrid, 256>>>(b2, M);
    mma_gemm_kernel<<<gemmGrid, 256, GEMM_SMEM_L>>>(nullptr, out, M, 1, 2, 0, 1);
    gather_kernel<<<gatherGrid, 256>>>(b3, M);

    mma_gemm_kernel<<<gemmGrid, 256, GEMM_SMEM_H>>>(nullptr, out, M, 1, 3, 1, 2);
}